// round 14
// baseline (speedup 1.0000x reference)
#include <cuda_runtime.h>
#include <cuda_bf16.h>
#include <cstdint>
#include <cfloat>
#include <math.h>

#define Q 8192
#define S 4096
#define C 1024
#define WAY 64
#define KNN 5

// output layout: tuple flattened in return order (float32)
constexpr int OFF_CLS  = 0;                  // [Q,64]
constexpr int OFF_IDX  = Q * WAY;            // [Q,5]
constexpr int OFF_DIST = OFF_IDX + Q * KNN;  // [Q,5]
constexpr int OFF_PRED = OFF_DIST + Q * KNN; // [Q]
constexpr int OFF_SC   = OFF_PRED + Q;       // [Q,64]

#define SPLITS 4               // s-splits of 1024 supports -> 256 CTAs = 1 full wave
#define NSUB 8                 // 128-support subtiles per split
#define TOPC 5
#define RESC 10
#define NCAND (SPLITS * TOPC)  // 20
#define RS 80                  // smem row stride (64B data + 16B pad)
#define NST 4                  // cp.async pipeline stages

typedef unsigned long long u64;

// scratch (device globals: allocation-free)
__device__ float          g_qn[Q * C];
__device__ float          g_sn[S * C];
__device__ __nv_bfloat16  g_qb[Q * C];
__device__ __nv_bfloat16  g_sb[S * C];
__device__ float          g_protoT[C * WAY];   // fp32 prototypes, k-major
__device__ float          g_ppart[WAY * 8 * C];
__device__ int            g_pcnt[WAY * 8];
__device__ u64            g_pkey[Q * NCAND];

__device__ __forceinline__ uint32_t smem_to_u32(const void* p) {
    uint32_t a;
    asm("{ .reg .u64 t; cvta.to.shared.u64 t, %1; cvt.u32.u64 %0, t; }" : "=r"(a) : "l"(p));
    return a;
}
#define LDSM_X4(r0, r1, r2, r3, addr) \
    asm volatile("ldmatrix.sync.aligned.m8n8.x4.shared.b16 {%0,%1,%2,%3}, [%4];" \
                 : "=r"(r0), "=r"(r1), "=r"(r2), "=r"(r3) : "r"(addr))
#define MMA_BF16(c, a, b) \
    asm volatile("mma.sync.aligned.m16n8k16.row.col.f32.bf16.bf16.f32 " \
                 "{%0,%1,%2,%3}, {%4,%5,%6,%7}, {%8,%9}, {%0,%1,%2,%3};" \
                 : "+f"((c)[0]), "+f"((c)[1]), "+f"((c)[2]), "+f"((c)[3]) \
                 : "r"((a)[0]), "r"((a)[1]), "r"((a)[2]), "r"((a)[3]), "r"((b)[0]), "r"((b)[1]))
#define CP_ASYNC16(dst, src) \
    asm volatile("cp.async.cg.shared.global [%0], [%1], 16;" :: "r"(dst), "l"(src))
#define CP_COMMIT() asm volatile("cp.async.commit_group;" ::: "memory")
#define CP_WAIT2()  asm volatile("cp.async.wait_group 2;" ::: "memory")

// packed top-k key: ordered-float (desc) || ~idx — one u64 compare == jax tie rule
__device__ __forceinline__ u64 mkkey(float v, int idx) {
    uint32_t u = __float_as_uint(v);
    u = (u & 0x80000000u) ? ~u : (u | 0x80000000u);
    return ((u64)u << 32) | (u64)(0xFFFFFFFFu - (uint32_t)idx);
}
template <int K>
__device__ __forceinline__ void insKey(u64* lst, u64 k) {
    if (k <= lst[K - 1]) return;
    bool b[K];
#pragma unroll
    for (int r = 0; r < K; r++) b[r] = k > lst[r];
#pragma unroll
    for (int r = K - 1; r > 0; r--) lst[r] = b[r - 1] ? lst[r - 1] : (b[r] ? k : lst[r]);
    if (b[0]) lst[0] = k;
}
__device__ __forceinline__ bool better(float x, int xi, float v, int vi) {
    return (x > v) || (x == v && xi < vi);
}
template <int K>
__device__ __forceinline__ void insertK(float* v, int* id, float x, int xi) {
    if (!better(x, xi, v[K - 1], id[K - 1])) return;
    bool b[K];
#pragma unroll
    for (int r = 0; r < K; r++) b[r] = better(x, xi, v[r], id[r]);
#pragma unroll
    for (int r = K - 1; r > 0; r--) {
        v[r]  = b[r - 1] ? v[r - 1]  : (b[r] ? x  : v[r]);
        id[r] = b[r - 1] ? id[r - 1] : (b[r] ? xi : id[r]);
    }
    if (b[0]) { v[0] = x; id[0] = xi; }
}

// ============================================================
// 1) row L2-normalize + bf16 copies — warp per row
// ============================================================
__global__ void __launch_bounds__(256) normalize_kernel(const float* __restrict__ qimg,
                                                        const float* __restrict__ simg) {
    const int t = threadIdx.x, lane = t & 31;
    const int row = blockIdx.x * 8 + (t >> 5);
    const float* src; float* dst; __nv_bfloat16* bdst;
    if (row < Q) { src = qimg + (size_t)row * C;       dst = g_qn + (size_t)row * C; bdst = g_qb + (size_t)row * C; }
    else         { src = simg + (size_t)(row - Q) * C; dst = g_sn + (size_t)(row - Q) * C; bdst = g_sb + (size_t)(row - Q) * C; }

    float4 v[8];
    float ss = 0.f;
#pragma unroll
    for (int i = 0; i < 8; i++) {
        v[i] = ((const float4*)src)[i * 32 + lane];
        ss += v[i].x * v[i].x + v[i].y * v[i].y + v[i].z * v[i].z + v[i].w * v[i].w;
    }
#pragma unroll
    for (int o = 16; o > 0; o >>= 1) ss += __shfl_xor_sync(0xffffffffu, ss, o);
    const float dn = fmaxf(sqrtf(ss), 1e-12f);
#pragma unroll
    for (int i = 0; i < 8; i++) {
        float4 o4;
        o4.x = v[i].x / dn; o4.y = v[i].y / dn; o4.z = v[i].z / dn; o4.w = v[i].w / dn;
        ((float4*)dst)[i * 32 + lane] = o4;
        __nv_bfloat162 b0, b1;
        b0.x = __float2bfloat16(o4.x); b0.y = __float2bfloat16(o4.y);
        b1.x = __float2bfloat16(o4.z); b1.y = __float2bfloat16(o4.w);
        ((__nv_bfloat162*)bdst)[(i * 32 + lane) * 2]     = b0;
        ((__nv_bfloat162*)bdst)[(i * 32 + lane) * 2 + 1] = b1;
    }
}

// ============================================================
// 2a) prototype partial sums: grid (64 classes, 8 s-stripes)
// ============================================================
__global__ void __launch_bounds__(256) proto_part_kernel(const int* __restrict__ labels) {
    __shared__ int slab[512];
    const int w = blockIdx.x, p = blockIdx.y, t = threadIdx.x;
    const int s0 = p * 512;
    for (int i = t; i < 512; i += 256) slab[i] = labels[s0 + i];
    __syncthreads();
    float ax = 0.f, ay = 0.f, az = 0.f, aw = 0.f;
    int cnt = 0;
    for (int s = 0; s < 512; s++) {
        if (slab[s] == w) {
            float4 v = ((const float4*)(g_sn + (size_t)(s0 + s) * C))[t];
            ax += v.x; ay += v.y; az += v.z; aw += v.w; cnt++;
        }
    }
    ((float4*)(g_ppart + ((size_t)w * 8 + p) * C))[t] = make_float4(ax, ay, az, aw);
    if (t == 0) g_pcnt[w * 8 + p] = cnt;
}

// ============================================================
// 2b) combine partials (fixed order), mean, l2norm -> fp32 k-major protoT
// ============================================================
__global__ void __launch_bounds__(256) proto_combine_kernel() {
    __shared__ float red[9];
    const int w = blockIdx.x, t = threadIdx.x;
    float ax = 0.f, ay = 0.f, az = 0.f, aw = 0.f;
    int cnt = 0;
#pragma unroll
    for (int p = 0; p < 8; p++) {
        float4 v = ((const float4*)(g_ppart + ((size_t)w * 8 + p) * C))[t];
        ax += v.x; ay += v.y; az += v.z; aw += v.w;
        cnt += g_pcnt[w * 8 + p];
    }
    const float fc = (float)(cnt > 0 ? cnt : 1);
    ax /= fc; ay /= fc; az /= fc; aw /= fc;
    float ss = ax * ax + ay * ay + az * az + aw * aw;
#pragma unroll
    for (int o = 16; o > 0; o >>= 1) ss += __shfl_xor_sync(0xffffffffu, ss, o);
    if ((t & 31) == 0) red[t >> 5] = ss;
    __syncthreads();
    if (t == 0) {
        float s = 0.f;
#pragma unroll
        for (int i = 0; i < 8; i++) s += red[i];
        red[8] = fmaxf(sqrtf(s), 1e-12f);
    }
    __syncthreads();
    const float dn = red[8];
    const int c0 = t * 4;
    g_protoT[(c0 + 0) * WAY + w] = ax / dn;
    g_protoT[(c0 + 1) * WAY + w] = ay / dn;
    g_protoT[(c0 + 2) * WAY + w] = az / dn;
    g_protoT[(c0 + 3) * WAY + w] = aw / dn;
}

// ============================================================
// 3) bf16 HMMA sim GEMM — R6 loop + unroll-2 chunk loop; SPLITS=4, 1 wave
//    grid (64 q-tiles, 4 s-splits), 256 threads (4m x 2n warps), 2 CTA/SM
// ============================================================
constexpr int STAGE = 128 * RS;              // 10240 B per operand stage
constexpr int SM_A  = 0;                     // 4 stages A
constexpr int SM_B  = NST * STAGE;           // 4 stages B
constexpr int SM_DK = 2 * NST * STAGE;       // 128 x TOPC u64
constexpr int SM_TOTAL_SIM = SM_DK + 128 * TOPC * 8;   // 87040

__global__ void __launch_bounds__(256, 2) sim_topk_kernel() {
    extern __shared__ __align__(16) unsigned char smem[];
    const uint32_t sbase = smem_to_u32(smem);
    const int t = threadIdx.x;
    const int lane = t & 31, wid = t >> 5;
    const int warp_m = wid & 3, warp_n = wid >> 2;
    const int qb = blockIdx.x * 128;
    const int split = blockIdx.y;

    // g2s: thread covers rows r0 and r0+64, 16B segment s0 of the 64B chunk row
    const int r0 = t >> 2, s0 = t & 3;
    const char* gqA = (const char*)g_qb + (size_t)(qb + r0) * 2048 + s0 * 16;
    const char* gqB = (const char*)g_qb + (size_t)(qb + r0 + 64) * 2048 + s0 * 16;
    const uint32_t dA0 = sbase + SM_A + r0 * RS + s0 * 16;
    const uint32_t dA1 = sbase + SM_A + (r0 + 64) * RS + s0 * 16;
    const uint32_t dB0 = sbase + SM_B + r0 * RS + s0 * 16;
    const uint32_t dB1 = sbase + SM_B + (r0 + 64) * RS + s0 * 16;

    // ldmatrix offsets
    const uint32_t aoff0 = sbase + SM_A + (warp_m * 32 + (lane & 15)) * RS + (lane >> 4) * 16;
    const uint32_t boffN = sbase + SM_B + (warp_n * 64 + (lane & 7) + ((lane & 16) ? 8 : 0)) * RS +
                           ((lane >> 3) & 1) * 16;

    u64 key[4][TOPC];
#pragma unroll
    for (int s = 0; s < 4; s++)
#pragma unroll
        for (int r = 0; r < TOPC; r++) key[s][r] = 0;

    for (int st = 0; st < NSUB; st++) {
        const int sr = split * (NSUB * 128) + st * 128;
        const char* gsA = (const char*)g_sb + (size_t)(sr + r0) * 2048 + s0 * 16;
        const char* gsB = (const char*)g_sb + (size_t)(sr + r0 + 64) * 2048 + s0 * 16;
        float c[2][8][4];
#pragma unroll
        for (int mf = 0; mf < 2; mf++)
#pragma unroll
            for (int nf = 0; nf < 8; nf++)
#pragma unroll
                for (int k = 0; k < 4; k++) c[mf][nf][k] = 0.f;

        // prologue: stages 0..2
#pragma unroll
        for (int p = 0; p < NST - 1; p++) {
            const uint32_t so = p * STAGE;
            CP_ASYNC16(dA0 + so, gqA + p * 64);
            CP_ASYNC16(dA1 + so, gqB + p * 64);
            CP_ASYNC16(dB0 + so, gsA + p * 64);
            CP_ASYNC16(dB1 + so, gsB + p * 64);
            CP_COMMIT();
        }

#pragma unroll 2
        for (int cc = 0; cc < 32; cc++) {
            CP_WAIT2();
            __syncthreads();
            if (cc < 29) {
                const uint32_t so = ((cc + 3) & 3) * STAGE;
                CP_ASYNC16(dA0 + so, gqA + (cc + 3) * 64);
                CP_ASYNC16(dA1 + so, gqB + (cc + 3) * 64);
                CP_ASYNC16(dB0 + so, gsA + (cc + 3) * 64);
                CP_ASYNC16(dB1 + so, gsB + (cc + 3) * 64);
            }
            CP_COMMIT();
            const uint32_t so = (cc & 3) * STAGE;
#pragma unroll
            for (int ks = 0; ks < 2; ks++) {
                uint32_t af[2][4], bf[8][2];
#pragma unroll
                for (int mf = 0; mf < 2; mf++)
                    LDSM_X4(af[mf][0], af[mf][1], af[mf][2], af[mf][3],
                            aoff0 + so + mf * 16 * RS + ks * 32);
#pragma unroll
                for (int np = 0; np < 4; np++)
                    LDSM_X4(bf[np * 2][0], bf[np * 2][1], bf[np * 2 + 1][0], bf[np * 2 + 1][1],
                            boffN + so + np * 16 * RS + ks * 32);
#pragma unroll
                for (int mf = 0; mf < 2; mf++)
#pragma unroll
                    for (int nf = 0; nf < 8; nf++)
                        MMA_BF16(c[mf][nf], af[mf], bf[nf]);
            }
        }

        // fold subtile into packed top-5 lists
#pragma unroll
        for (int mf = 0; mf < 2; mf++)
#pragma unroll
            for (int nf = 0; nf < 8; nf++) {
                const int col = sr + warp_n * 64 + nf * 8 + (lane & 3) * 2;
                insKey<TOPC>(key[mf * 2],     mkkey(c[mf][nf][0], col));
                insKey<TOPC>(key[mf * 2],     mkkey(c[mf][nf][1], col + 1));
                insKey<TOPC>(key[mf * 2 + 1], mkkey(c[mf][nf][2], col));
                insKey<TOPC>(key[mf * 2 + 1], mkkey(c[mf][nf][3], col + 1));
            }
        __syncthreads();  // protect next subtile's prologue overwrites
    }

    // quad merge (lanes sharing rows differ only in lane&3)
#pragma unroll
    for (int off = 1; off < 4; off <<= 1) {
#pragma unroll
        for (int s = 0; s < 4; s++) {
            u64 ok[TOPC];
#pragma unroll
            for (int r = 0; r < TOPC; r++) ok[r] = __shfl_xor_sync(0xffffffffu, key[s][r], off);
#pragma unroll
            for (int r = 0; r < TOPC; r++) insKey<TOPC>(key[s], ok[r]);
        }
    }

    // cross-warp_n merge via smem, then write per-(query, split) key partials
    u64* dkey = (u64*)(smem + SM_DK);
    const int g = lane >> 2;
    if (warp_n == 1 && (lane & 3) == 0) {
#pragma unroll
        for (int s = 0; s < 4; s++) {
            const int row = warp_m * 32 + (s >> 1) * 16 + (s & 1) * 8 + g;
#pragma unroll
            for (int r = 0; r < TOPC; r++) dkey[row * TOPC + r] = key[s][r];
        }
    }
    __syncthreads();
    if (warp_n == 0 && (lane & 3) == 0) {
#pragma unroll
        for (int s = 0; s < 4; s++) {
            const int row = warp_m * 32 + (s >> 1) * 16 + (s & 1) * 8 + g;
#pragma unroll
            for (int r = 0; r < TOPC; r++) insKey<TOPC>(key[s], dkey[row * TOPC + r]);
            const size_t base = ((size_t)(qb + row) * SPLITS + split) * TOPC;
#pragma unroll
            for (int r = 0; r < TOPC; r++) g_pkey[base + r] = key[s][r];
        }
    }
}

// ============================================================
// 4) merge (20 keys -> top-10) + exact fp32 rescore, 2 queries per warp
//    16 lanes per query; grid Q/16 blocks of 256
// ============================================================
__global__ void __launch_bounds__(256) merge_rescore_kernel(const int* __restrict__ labels,
                                                            float* __restrict__ out) {
    __shared__ int   ssel[16][RESC];
    __shared__ float sres[16][RESC];
    const int t = threadIdx.x, wid = t >> 5, lane = t & 31;
    const int half = lane >> 4, lid = lane & 15;       // half-warp handles one query
    const int qi = wid * 2 + half;                     // query slot in block (0..15)
    const int q = blockIdx.x * 16 + qi;
    const uint32_t hmask = half ? 0xFFFF0000u : 0x0000FFFFu;

    u64 k0 = (lid < NCAND) ? g_pkey[(size_t)q * NCAND + lid] : 0;
    u64 k1 = (lid + 16 < NCAND) ? g_pkey[(size_t)q * NCAND + lid + 16] : 0;

#pragma unroll
    for (int i = 0; i < RESC; i++) {
        u64 m = k0 > k1 ? k0 : k1;
#pragma unroll
        for (int off = 8; off > 0; off >>= 1) {
            u64 o = __shfl_xor_sync(hmask, m, off);
            if (o > m) m = o;
        }
        if (lid == 0) ssel[qi][i] = (int)(0xFFFFFFFFu - (uint32_t)m);
        if (k0 == m) k0 = 0;
        if (k1 == m) k1 = 0;
    }
    __syncwarp();

    // each of the 16 lanes covers 64 elems of the dot product (16 float4)
    float4 qv[16];
#pragma unroll
    for (int k = 0; k < 16; k++)
        qv[k] = *(const float4*)(g_qn + (size_t)q * C + k * 64 + lid * 4);

#pragma unroll 1
    for (int c = 0; c < RESC; c++) {
        const int si = ssel[qi][c];
        const float* srow = g_sn + (size_t)si * C;
        float acc = 0.f;
#pragma unroll
        for (int k = 0; k < 16; k++) {
            float4 sv = *(const float4*)(srow + k * 64 + lid * 4);
            acc = fmaf(qv[k].x, sv.x, acc);
            acc = fmaf(qv[k].y, sv.y, acc);
            acc = fmaf(qv[k].z, sv.z, acc);
            acc = fmaf(qv[k].w, sv.w, acc);
        }
#pragma unroll
        for (int o = 8; o > 0; o >>= 1) acc += __shfl_xor_sync(hmask, acc, o);
        if (lid == 0) sres[qi][c] = acc;
    }
    __syncwarp();

    if (lid == 0) {
        float v5[5]; int i5[5];
#pragma unroll
        for (int r = 0; r < 5; r++) { v5[r] = -FLT_MAX; i5[r] = 0x7fffffff; }
#pragma unroll
        for (int c = 0; c < RESC; c++) insertK<5>(v5, i5, sres[qi][c], ssel[qi][c]);
#pragma unroll
        for (int r = 0; r < 5; r++) {
            out[OFF_IDX + q * 5 + r] = (float)i5[r];
            out[OFF_DIST + q * 5 + r] = 1.0f - v5[r];
        }
        int lab[5];
#pragma unroll
        for (int r = 0; r < 5; r++) lab[r] = labels[i5[r]];
        int bestc = 0, bestl = 1 << 30;
#pragma unroll
        for (int r = 0; r < 5; r++) {
            int cn = 0;
#pragma unroll
            for (int j = 0; j < 5; j++) cn += (lab[j] == lab[r]);
            if (cn > bestc || (cn == bestc && lab[r] < bestl)) { bestc = cn; bestl = lab[r]; }
        }
        out[OFF_PRED + q] = (float)bestl;
    }
}

// ============================================================
// 5) fp32 scores = q_norm @ protoT -> classification_scores (10x) + scores
// ============================================================
__global__ void __launch_bounds__(256) scores_kernel(float* __restrict__ out) {
    __shared__ __align__(16) float Aq[16][64];
    __shared__ __align__(16) float Bp[16][64];
    const int t = threadIdx.x;
    const int tx = t & 15, ty = t >> 4;
    const int qb = blockIdx.x * 64;
    float acc[4][4];
#pragma unroll
    for (int i = 0; i < 4; i++)
#pragma unroll
        for (int j = 0; j < 4; j++) acc[i][j] = 0.f;

    const int arow = t >> 2, akq = (t & 3) << 2;
    const int bkr = t >> 4, bwq = (t & 15) << 2;
    for (int kc = 0; kc < C; kc += 16) {
        float4 a = *(const float4*)(g_qn + (size_t)(qb + arow) * C + kc + akq);
        Aq[akq + 0][arow] = a.x; Aq[akq + 1][arow] = a.y;
        Aq[akq + 2][arow] = a.z; Aq[akq + 3][arow] = a.w;
        *(float4*)(&Bp[bkr][bwq]) = *(const float4*)(g_protoT + (size_t)(kc + bkr) * WAY + bwq);
        __syncthreads();
#pragma unroll
        for (int k = 0; k < 16; k++) {
            float4 av = *(const float4*)(&Aq[k][ty * 4]);
            float4 bv = *(const float4*)(&Bp[k][tx * 4]);
            float aa[4] = {av.x, av.y, av.z, av.w};
            float bb[4] = {bv.x, bv.y, bv.z, bv.w};
#pragma unroll
            for (int i = 0; i < 4; i++)
#pragma unroll
                for (int j = 0; j < 4; j++) acc[i][j] = fmaf(aa[i], bb[j], acc[i][j]);
        }
        __syncthreads();
    }
#pragma unroll
    for (int i = 0; i < 4; i++) {
        int q = qb + ty * 4 + i;
#pragma unroll
        for (int j = 0; j < 4; j++) {
            int w = tx * 4 + j;
            float s = acc[i][j];
            out[OFF_SC + (size_t)q * WAY + w] = s;
            out[OFF_CLS + (size_t)q * WAY + w] = 10.0f * s;
        }
    }
}

extern "C" void kernel_launch(void* const* d_in, const int* in_sizes, int n_in,
                              void* d_out, int out_size) {
    const float* simg   = (const float*)d_in[0];
    const int*   labels = (const int*)d_in[1];
    const float* qimg   = (const float*)d_in[2];
    float* out = (float*)d_out;

    cudaFuncSetAttribute(sim_topk_kernel, cudaFuncAttributeMaxDynamicSharedMemorySize, SM_TOTAL_SIM);

    // fork: proto chain + scores run on side stream, overlapped with sim
    cudaStream_t s2;
    cudaStreamCreateWithFlags(&s2, cudaStreamNonBlocking);
    cudaEvent_t evA, evB;
    cudaEventCreateWithFlags(&evA, cudaEventDisableTiming);
    cudaEventCreateWithFlags(&evB, cudaEventDisableTiming);

    normalize_kernel<<<(Q + S) / 8, 256>>>(qimg, simg);
    cudaEventRecord(evA, 0);

    cudaStreamWaitEvent(s2, evA, 0);
    proto_part_kernel<<<dim3(WAY, 8), 256, 0, s2>>>(labels);
    proto_combine_kernel<<<WAY, 256, 0, s2>>>();
    scores_kernel<<<Q / 64, 256, 0, s2>>>(out);
    cudaEventRecord(evB, s2);

    sim_topk_kernel<<<dim3(Q / 128, SPLITS), 256, SM_TOTAL_SIM>>>();
    merge_rescore_kernel<<<Q / 16, 256>>>(labels, out);
    cudaStreamWaitEvent(0, evB, 0);
}

// round 15
// speedup vs baseline: 1.0438x; 1.0438x over previous
#include <cuda_runtime.h>
#include <cuda_bf16.h>
#include <cstdint>
#include <cfloat>
#include <math.h>

#define Q 8192
#define S 4096
#define C 1024
#define WAY 64
#define KNN 5

// output layout: tuple flattened in return order (float32)
constexpr int OFF_CLS  = 0;                  // [Q,64]
constexpr int OFF_IDX  = Q * WAY;            // [Q,5]
constexpr int OFF_DIST = OFF_IDX + Q * KNN;  // [Q,5]
constexpr int OFF_PRED = OFF_DIST + Q * KNN; // [Q]
constexpr int OFF_SC   = OFF_PRED + Q;       // [Q,64]

#define SPLITS 4               // s-splits of 1024 supports -> 256 CTAs = 1 full wave
#define NSUB 8                 // 128-support subtiles per split
#define TOPC 5
#define RESC 10
#define NCAND (SPLITS * TOPC)  // 20
#define RS 80                  // smem row stride (64B data + 16B pad)
#define NST 4                  // cp.async pipeline stages

typedef unsigned long long u64;

// scratch (device globals: allocation-free)
__device__ float          g_qn[Q * C];
__device__ float          g_sn[S * C];
__device__ __nv_bfloat16  g_qb[Q * C];
__device__ __nv_bfloat16  g_sb[S * C];
__device__ float          g_protoT[C * WAY];   // fp32 prototypes, k-major
__device__ float          g_ppart[WAY * 8 * C];
__device__ int            g_pcnt[WAY * 8];
__device__ u64            g_pkey[Q * NCAND];

__device__ __forceinline__ uint32_t smem_to_u32(const void* p) {
    uint32_t a;
    asm("{ .reg .u64 t; cvta.to.shared.u64 t, %1; cvt.u32.u64 %0, t; }" : "=r"(a) : "l"(p));
    return a;
}
#define LDSM_X4(r0, r1, r2, r3, addr) \
    asm volatile("ldmatrix.sync.aligned.m8n8.x4.shared.b16 {%0,%1,%2,%3}, [%4];" \
                 : "=r"(r0), "=r"(r1), "=r"(r2), "=r"(r3) : "r"(addr))
#define MMA_BF16(c, a, b) \
    asm volatile("mma.sync.aligned.m16n8k16.row.col.f32.bf16.bf16.f32 " \
                 "{%0,%1,%2,%3}, {%4,%5,%6,%7}, {%8,%9}, {%0,%1,%2,%3};" \
                 : "+f"((c)[0]), "+f"((c)[1]), "+f"((c)[2]), "+f"((c)[3]) \
                 : "r"((a)[0]), "r"((a)[1]), "r"((a)[2]), "r"((a)[3]), "r"((b)[0]), "r"((b)[1]))
#define CP_ASYNC16(dst, src) \
    asm volatile("cp.async.cg.shared.global [%0], [%1], 16;" :: "r"(dst), "l"(src))
#define CP_COMMIT() asm volatile("cp.async.commit_group;" ::: "memory")
#define CP_WAIT2()  asm volatile("cp.async.wait_group 2;" ::: "memory")

// packed top-k key: ordered-float (desc) || ~idx — one u64 compare == jax tie rule
__device__ __forceinline__ u64 mkkey(float v, int idx) {
    uint32_t u = __float_as_uint(v);
    u = (u & 0x80000000u) ? ~u : (u | 0x80000000u);
    return ((u64)u << 32) | (u64)(0xFFFFFFFFu - (uint32_t)idx);
}
__device__ __forceinline__ float keyval(u64 k) {
    uint32_t u = (uint32_t)(k >> 32);
    return (u & 0x80000000u) ? __uint_as_float(u & 0x7fffffffu) : __uint_as_float(~u);
}
// sentinel: value -FLT_MAX, idx 0x7fffffff -> keyval() == -FLT_MAX (NOT NaN)
#define KEY_SENTINEL ((((u64)0x00800000u) << 32) | 0x80000000ull)

template <int K>
__device__ __forceinline__ void insKey(u64* lst, u64 k) {
    if (k <= lst[K - 1]) return;
    bool b[K];
#pragma unroll
    for (int r = 0; r < K; r++) b[r] = k > lst[r];
#pragma unroll
    for (int r = K - 1; r > 0; r--) lst[r] = b[r - 1] ? lst[r - 1] : (b[r] ? k : lst[r]);
    if (b[0]) lst[0] = k;
}
__device__ __forceinline__ bool better(float x, int xi, float v, int vi) {
    return (x > v) || (x == v && xi < vi);
}
template <int K>
__device__ __forceinline__ void insertK(float* v, int* id, float x, int xi) {
    if (!better(x, xi, v[K - 1], id[K - 1])) return;
    bool b[K];
#pragma unroll
    for (int r = 0; r < K; r++) b[r] = better(x, xi, v[r], id[r]);
#pragma unroll
    for (int r = K - 1; r > 0; r--) {
        v[r]  = b[r - 1] ? v[r - 1]  : (b[r] ? x  : v[r]);
        id[r] = b[r - 1] ? id[r - 1] : (b[r] ? xi : id[r]);
    }
    if (b[0]) { v[0] = x; id[0] = xi; }
}

// ============================================================
// 1) row L2-normalize + bf16 copies — warp per row
// ============================================================
__global__ void __launch_bounds__(256) normalize_kernel(const float* __restrict__ qimg,
                                                        const float* __restrict__ simg) {
    const int t = threadIdx.x, lane = t & 31;
    const int row = blockIdx.x * 8 + (t >> 5);
    const float* src; float* dst; __nv_bfloat16* bdst;
    if (row < Q) { src = qimg + (size_t)row * C;       dst = g_qn + (size_t)row * C; bdst = g_qb + (size_t)row * C; }
    else         { src = simg + (size_t)(row - Q) * C; dst = g_sn + (size_t)(row - Q) * C; bdst = g_sb + (size_t)(row - Q) * C; }

    float4 v[8];
    float ss = 0.f;
#pragma unroll
    for (int i = 0; i < 8; i++) {
        v[i] = ((const float4*)src)[i * 32 + lane];
        ss += v[i].x * v[i].x + v[i].y * v[i].y + v[i].z * v[i].z + v[i].w * v[i].w;
    }
#pragma unroll
    for (int o = 16; o > 0; o >>= 1) ss += __shfl_xor_sync(0xffffffffu, ss, o);
    const float dn = fmaxf(sqrtf(ss), 1e-12f);
#pragma unroll
    for (int i = 0; i < 8; i++) {
        float4 o4;
        o4.x = v[i].x / dn; o4.y = v[i].y / dn; o4.z = v[i].z / dn; o4.w = v[i].w / dn;
        ((float4*)dst)[i * 32 + lane] = o4;
        __nv_bfloat162 b0, b1;
        b0.x = __float2bfloat16(o4.x); b0.y = __float2bfloat16(o4.y);
        b1.x = __float2bfloat16(o4.z); b1.y = __float2bfloat16(o4.w);
        ((__nv_bfloat162*)bdst)[(i * 32 + lane) * 2]     = b0;
        ((__nv_bfloat162*)bdst)[(i * 32 + lane) * 2 + 1] = b1;
    }
}

// ============================================================
// 2a) prototype partial sums: grid (64 classes, 8 s-stripes)
// ============================================================
__global__ void __launch_bounds__(256) proto_part_kernel(const int* __restrict__ labels) {
    __shared__ int slab[512];
    const int w = blockIdx.x, p = blockIdx.y, t = threadIdx.x;
    const int s0 = p * 512;
    for (int i = t; i < 512; i += 256) slab[i] = labels[s0 + i];
    __syncthreads();
    float ax = 0.f, ay = 0.f, az = 0.f, aw = 0.f;
    int cnt = 0;
    for (int s = 0; s < 512; s++) {
        if (slab[s] == w) {
            float4 v = ((const float4*)(g_sn + (size_t)(s0 + s) * C))[t];
            ax += v.x; ay += v.y; az += v.z; aw += v.w; cnt++;
        }
    }
    ((float4*)(g_ppart + ((size_t)w * 8 + p) * C))[t] = make_float4(ax, ay, az, aw);
    if (t == 0) g_pcnt[w * 8 + p] = cnt;
}

// ============================================================
// 2b) combine partials (fixed order), mean, l2norm -> fp32 k-major protoT
// ============================================================
__global__ void __launch_bounds__(256) proto_combine_kernel() {
    __shared__ float red[9];
    const int w = blockIdx.x, t = threadIdx.x;
    float ax = 0.f, ay = 0.f, az = 0.f, aw = 0.f;
    int cnt = 0;
#pragma unroll
    for (int p = 0; p < 8; p++) {
        float4 v = ((const float4*)(g_ppart + ((size_t)w * 8 + p) * C))[t];
        ax += v.x; ay += v.y; az += v.z; aw += v.w;
        cnt += g_pcnt[w * 8 + p];
    }
    const float fc = (float)(cnt > 0 ? cnt : 1);
    ax /= fc; ay /= fc; az /= fc; aw /= fc;
    float ss = ax * ax + ay * ay + az * az + aw * aw;
#pragma unroll
    for (int o = 16; o > 0; o >>= 1) ss += __shfl_xor_sync(0xffffffffu, ss, o);
    if ((t & 31) == 0) red[t >> 5] = ss;
    __syncthreads();
    if (t == 0) {
        float s = 0.f;
#pragma unroll
        for (int i = 0; i < 8; i++) s += red[i];
        red[8] = fmaxf(sqrtf(s), 1e-12f);
    }
    __syncthreads();
    const float dn = red[8];
    const int c0 = t * 4;
    g_protoT[(c0 + 0) * WAY + w] = ax / dn;
    g_protoT[(c0 + 1) * WAY + w] = ay / dn;
    g_protoT[(c0 + 2) * WAY + w] = az / dn;
    g_protoT[(c0 + 3) * WAY + w] = aw / dn;
}

// ============================================================
// 3) bf16 HMMA sim GEMM — R13 loop verbatim + threshold-prefiltered fold
//    grid (64 q-tiles, 4 s-splits), 256 threads (4m x 2n warps), 2 CTA/SM
// ============================================================
constexpr int STAGE = 128 * RS;              // 10240 B per operand stage
constexpr int SM_A  = 0;                     // 4 stages A
constexpr int SM_B  = NST * STAGE;           // 4 stages B
constexpr int SM_DK = 2 * NST * STAGE;       // 128 x TOPC u64
constexpr int SM_TOTAL_SIM = SM_DK + 128 * TOPC * 8;   // 87040

__global__ void __launch_bounds__(256, 2) sim_topk_kernel() {
    extern __shared__ __align__(16) unsigned char smem[];
    const uint32_t sbase = smem_to_u32(smem);
    const int t = threadIdx.x;
    const int lane = t & 31, wid = t >> 5;
    const int warp_m = wid & 3, warp_n = wid >> 2;
    const int qb = blockIdx.x * 128;
    const int split = blockIdx.y;

    // g2s: thread covers rows r0 and r0+64, 16B segment s0 of the 64B chunk row
    const int r0 = t >> 2, s0 = t & 3;
    const char* gqA = (const char*)g_qb + (size_t)(qb + r0) * 2048 + s0 * 16;
    const char* gqB = (const char*)g_qb + (size_t)(qb + r0 + 64) * 2048 + s0 * 16;
    const uint32_t dA0 = sbase + SM_A + r0 * RS + s0 * 16;
    const uint32_t dA1 = sbase + SM_A + (r0 + 64) * RS + s0 * 16;
    const uint32_t dB0 = sbase + SM_B + r0 * RS + s0 * 16;
    const uint32_t dB1 = sbase + SM_B + (r0 + 64) * RS + s0 * 16;

    // ldmatrix offsets
    const uint32_t aoff0 = sbase + SM_A + (warp_m * 32 + (lane & 15)) * RS + (lane >> 4) * 16;
    const uint32_t boffN = sbase + SM_B + (warp_n * 64 + (lane & 7) + ((lane & 16) ? 8 : 0)) * RS +
                           ((lane >> 3) & 1) * 16;

    u64 key[4][TOPC];
    float thr[4];
#pragma unroll
    for (int s = 0; s < 4; s++) {
        thr[s] = -FLT_MAX;
#pragma unroll
        for (int r = 0; r < TOPC; r++) key[s][r] = KEY_SENTINEL;
    }

    for (int st = 0; st < NSUB; st++) {
        const int sr = split * (NSUB * 128) + st * 128;
        const char* gsA = (const char*)g_sb + (size_t)(sr + r0) * 2048 + s0 * 16;
        const char* gsB = (const char*)g_sb + (size_t)(sr + r0 + 64) * 2048 + s0 * 16;
        float c[2][8][4];
#pragma unroll
        for (int mf = 0; mf < 2; mf++)
#pragma unroll
            for (int nf = 0; nf < 8; nf++)
#pragma unroll
                for (int k = 0; k < 4; k++) c[mf][nf][k] = 0.f;

        // prologue: stages 0..2
#pragma unroll
        for (int p = 0; p < NST - 1; p++) {
            const uint32_t so = p * STAGE;
            CP_ASYNC16(dA0 + so, gqA + p * 64);
            CP_ASYNC16(dA1 + so, gqB + p * 64);
            CP_ASYNC16(dB0 + so, gsA + p * 64);
            CP_ASYNC16(dB1 + so, gsB + p * 64);
            CP_COMMIT();
        }

        for (int cc = 0; cc < 32; cc++) {
            CP_WAIT2();
            __syncthreads();
            if (cc < 29) {
                const uint32_t so = ((cc + 3) & 3) * STAGE;
                CP_ASYNC16(dA0 + so, gqA + (cc + 3) * 64);
                CP_ASYNC16(dA1 + so, gqB + (cc + 3) * 64);
                CP_ASYNC16(dB0 + so, gsA + (cc + 3) * 64);
                CP_ASYNC16(dB1 + so, gsB + (cc + 3) * 64);
            }
            CP_COMMIT();
            const uint32_t so = (cc & 3) * STAGE;
#pragma unroll
            for (int ks = 0; ks < 2; ks++) {
                uint32_t af[2][4], bf[8][2];
#pragma unroll
                for (int mf = 0; mf < 2; mf++)
                    LDSM_X4(af[mf][0], af[mf][1], af[mf][2], af[mf][3],
                            aoff0 + so + mf * 16 * RS + ks * 32);
#pragma unroll
                for (int np = 0; np < 4; np++)
                    LDSM_X4(bf[np * 2][0], bf[np * 2][1], bf[np * 2 + 1][0], bf[np * 2 + 1][1],
                            boffN + so + np * 16 * RS + ks * 32);
#pragma unroll
                for (int mf = 0; mf < 2; mf++)
#pragma unroll
                    for (int nf = 0; nf < 8; nf++)
                        MMA_BF16(c[mf][nf], af[mf], bf[nf]);
            }
        }

        // fold subtile into packed top-5 lists (threshold-prefiltered)
#pragma unroll
        for (int mf = 0; mf < 2; mf++)
#pragma unroll
            for (int nf = 0; nf < 8; nf++) {
                const int col = sr + warp_n * 64 + nf * 8 + (lane & 3) * 2;
                const int s0i = mf * 2, s1i = mf * 2 + 1;
                if (fmaxf(c[mf][nf][0], c[mf][nf][1]) > thr[s0i]) {
                    insKey<TOPC>(key[s0i], mkkey(c[mf][nf][0], col));
                    insKey<TOPC>(key[s0i], mkkey(c[mf][nf][1], col + 1));
                    thr[s0i] = keyval(key[s0i][TOPC - 1]);
                }
                if (fmaxf(c[mf][nf][2], c[mf][nf][3]) > thr[s1i]) {
                    insKey<TOPC>(key[s1i], mkkey(c[mf][nf][2], col));
                    insKey<TOPC>(key[s1i], mkkey(c[mf][nf][3], col + 1));
                    thr[s1i] = keyval(key[s1i][TOPC - 1]);
                }
            }
        __syncthreads();  // protect next subtile's prologue overwrites
    }

    // quad merge (lanes sharing rows differ only in lane&3)
#pragma unroll
    for (int off = 1; off < 4; off <<= 1) {
#pragma unroll
        for (int s = 0; s < 4; s++) {
            u64 ok[TOPC];
#pragma unroll
            for (int r = 0; r < TOPC; r++) ok[r] = __shfl_xor_sync(0xffffffffu, key[s][r], off);
#pragma unroll
            for (int r = 0; r < TOPC; r++) insKey<TOPC>(key[s], ok[r]);
        }
    }

    // cross-warp_n merge via smem, then write per-(query, split) key partials
    u64* dkey = (u64*)(smem + SM_DK);
    const int g = lane >> 2;
    if (warp_n == 1 && (lane & 3) == 0) {
#pragma unroll
        for (int s = 0; s < 4; s++) {
            const int row = warp_m * 32 + (s >> 1) * 16 + (s & 1) * 8 + g;
#pragma unroll
            for (int r = 0; r < TOPC; r++) dkey[row * TOPC + r] = key[s][r];
        }
    }
    __syncthreads();
    if (warp_n == 0 && (lane & 3) == 0) {
#pragma unroll
        for (int s = 0; s < 4; s++) {
            const int row = warp_m * 32 + (s >> 1) * 16 + (s & 1) * 8 + g;
#pragma unroll
            for (int r = 0; r < TOPC; r++) insKey<TOPC>(key[s], dkey[row * TOPC + r]);
            const size_t base = ((size_t)(qb + row) * SPLITS + split) * TOPC;
#pragma unroll
            for (int r = 0; r < TOPC; r++) g_pkey[base + r] = key[s][r];
        }
    }
}

// ============================================================
// 4) warp-parallel merge (20 keys -> top-10), exact fp32 rescore, emit
// ============================================================
__global__ void __launch_bounds__(256) merge_rescore_kernel(const int* __restrict__ labels,
                                                            float* __restrict__ out) {
    __shared__ int   ssel[8][RESC];
    __shared__ float sres[8][RESC];
    const int t = threadIdx.x, wid = t >> 5, lid = t & 31;
    const int q = blockIdx.x * 8 + wid;

    u64 k0 = (lid < NCAND) ? g_pkey[(size_t)q * NCAND + lid] : 0;

#pragma unroll
    for (int i = 0; i < RESC; i++) {
        u64 m = k0;
#pragma unroll
        for (int off = 16; off > 0; off >>= 1) {
            u64 o = __shfl_xor_sync(0xffffffffu, m, off);
            if (o > m) m = o;
        }
        if (lid == 0) ssel[wid][i] = (int)(0xFFFFFFFFu - (uint32_t)m);
        if (k0 == m) k0 = 0;
    }
    __syncwarp();

    float4 qv[8];
#pragma unroll
    for (int k = 0; k < 8; k++)
        qv[k] = *(const float4*)(g_qn + (size_t)q * C + k * 128 + lid * 4);

#pragma unroll 1
    for (int c = 0; c < RESC; c++) {
        const int si = ssel[wid][c];
        const float* srow = g_sn + (size_t)si * C;
        float acc = 0.f;
#pragma unroll
        for (int k = 0; k < 8; k++) {
            float4 sv = *(const float4*)(srow + k * 128 + lid * 4);
            acc = fmaf(qv[k].x, sv.x, acc);
            acc = fmaf(qv[k].y, sv.y, acc);
            acc = fmaf(qv[k].z, sv.z, acc);
            acc = fmaf(qv[k].w, sv.w, acc);
        }
#pragma unroll
        for (int o = 16; o > 0; o >>= 1) acc += __shfl_xor_sync(0xffffffffu, acc, o);
        if (lid == 0) sres[wid][c] = acc;
    }
    __syncwarp();

    if (lid == 0) {
        float v5[5]; int i5[5];
#pragma unroll
        for (int r = 0; r < 5; r++) { v5[r] = -FLT_MAX; i5[r] = 0x7fffffff; }
#pragma unroll
        for (int c = 0; c < RESC; c++) insertK<5>(v5, i5, sres[wid][c], ssel[wid][c]);
#pragma unroll
        for (int r = 0; r < 5; r++) {
            out[OFF_IDX + q * 5 + r] = (float)i5[r];
            out[OFF_DIST + q * 5 + r] = 1.0f - v5[r];
        }
        int lab[5];
#pragma unroll
        for (int r = 0; r < 5; r++) lab[r] = labels[i5[r]];
        int bestc = 0, bestl = 1 << 30;
#pragma unroll
        for (int r = 0; r < 5; r++) {
            int cn = 0;
#pragma unroll
            for (int j = 0; j < 5; j++) cn += (lab[j] == lab[r]);
            if (cn > bestc || (cn == bestc && lab[r] < bestl)) { bestc = cn; bestl = lab[r]; }
        }
        out[OFF_PRED + q] = (float)bestl;
    }
}

// ============================================================
// 5) fp32 scores = q_norm @ protoT -> classification_scores (10x) + scores
// ============================================================
__global__ void __launch_bounds__(256) scores_kernel(float* __restrict__ out) {
    __shared__ __align__(16) float Aq[16][64];
    __shared__ __align__(16) float Bp[16][64];
    const int t = threadIdx.x;
    const int tx = t & 15, ty = t >> 4;
    const int qb = blockIdx.x * 64;
    float acc[4][4];
#pragma unroll
    for (int i = 0; i < 4; i++)
#pragma unroll
        for (int j = 0; j < 4; j++) acc[i][j] = 0.f;

    const int arow = t >> 2, akq = (t & 3) << 2;
    const int bkr = t >> 4, bwq = (t & 15) << 2;
    for (int kc = 0; kc < C; kc += 16) {
        float4 a = *(const float4*)(g_qn + (size_t)(qb + arow) * C + kc + akq);
        Aq[akq + 0][arow] = a.x; Aq[akq + 1][arow] = a.y;
        Aq[akq + 2][arow] = a.z; Aq[akq + 3][arow] = a.w;
        *(float4*)(&Bp[bkr][bwq]) = *(const float4*)(g_protoT + (size_t)(kc + bkr) * WAY + bwq);
        __syncthreads();
#pragma unroll
        for (int k = 0; k < 16; k++) {
            float4 av = *(const float4*)(&Aq[k][ty * 4]);
            float4 bv = *(const float4*)(&Bp[k][tx * 4]);
            float aa[4] = {av.x, av.y, av.z, av.w};
            float bb[4] = {bv.x, bv.y, bv.z, bv.w};
#pragma unroll
            for (int i = 0; i < 4; i++)
#pragma unroll
                for (int j = 0; j < 4; j++) acc[i][j] = fmaf(aa[i], bb[j], acc[i][j]);
        }
        __syncthreads();
    }
#pragma unroll
    for (int i = 0; i < 4; i++) {
        int q = qb + ty * 4 + i;
#pragma unroll
        for (int j = 0; j < 4; j++) {
            int w = tx * 4 + j;
            float s = acc[i][j];
            out[OFF_SC + (size_t)q * WAY + w] = s;
            out[OFF_CLS + (size_t)q * WAY + w] = 10.0f * s;
        }
    }
}

extern "C" void kernel_launch(void* const* d_in, const int* in_sizes, int n_in,
                              void* d_out, int out_size) {
    const float* simg   = (const float*)d_in[0];
    const int*   labels = (const int*)d_in[1];
    const float* qimg   = (const float*)d_in[2];
    float* out = (float*)d_out;

    cudaFuncSetAttribute(sim_topk_kernel, cudaFuncAttributeMaxDynamicSharedMemorySize, SM_TOTAL_SIM);

    // fork: proto chain + scores run on side stream, overlapped with sim
    cudaStream_t s2;
    cudaStreamCreateWithFlags(&s2, cudaStreamNonBlocking);
    cudaEvent_t evA, evB;
    cudaEventCreateWithFlags(&evA, cudaEventDisableTiming);
    cudaEventCreateWithFlags(&evB, cudaEventDisableTiming);

    normalize_kernel<<<(Q + S) / 8, 256>>>(qimg, simg);
    cudaEventRecord(evA, 0);

    cudaStreamWaitEvent(s2, evA, 0);
    proto_part_kernel<<<dim3(WAY, 8), 256, 0, s2>>>(labels);
    proto_combine_kernel<<<WAY, 256, 0, s2>>>();
    scores_kernel<<<Q / 64, 256, 0, s2>>>(out);
    cudaEventRecord(evB, s2);

    sim_topk_kernel<<<dim3(Q / 128, SPLITS), 256, SM_TOTAL_SIM>>>();
    merge_rescore_kernel<<<Q / 8, 256>>>(labels, out);
    cudaStreamWaitEvent(0, evB, 0);
}

// round 16
// speedup vs baseline: 1.0676x; 1.0228x over previous
#include <cuda_runtime.h>
#include <cuda_bf16.h>
#include <cstdint>
#include <cfloat>
#include <math.h>

#define Q 8192
#define S 4096
#define C 1024
#define WAY 64
#define KNN 5

// output layout: tuple flattened in return order (float32)
constexpr int OFF_CLS  = 0;                  // [Q,64]
constexpr int OFF_IDX  = Q * WAY;            // [Q,5]
constexpr int OFF_DIST = OFF_IDX + Q * KNN;  // [Q,5]
constexpr int OFF_PRED = OFF_DIST + Q * KNN; // [Q]
constexpr int OFF_SC   = OFF_PRED + Q;       // [Q,64]

#define SPLITS 4               // s-splits of 1024 supports -> 256 CTAs = 1 full wave
#define NSUB 8                 // 128-support subtiles per split
#define TOPC 5
#define RESC 10
#define NCAND (SPLITS * TOPC)  // 20
#define RS 80                  // smem row stride (64B data + 16B pad)
#define NST 4                  // cp.async pipeline stages

typedef unsigned long long u64;

// scratch (device globals: allocation-free)
__device__ float          g_qn[Q * C];
__device__ float          g_sn[S * C];
__device__ __nv_bfloat16  g_qb[Q * C];
__device__ __nv_bfloat16  g_sb[S * C];
__device__ float          g_protoT[C * WAY];   // fp32 prototypes, k-major
__device__ float          g_ppart[WAY * 8 * C];
__device__ int            g_pcnt[WAY * 8];
__device__ u64            g_pkey[Q * NCAND];

__device__ __forceinline__ uint32_t smem_to_u32(const void* p) {
    uint32_t a;
    asm("{ .reg .u64 t; cvta.to.shared.u64 t, %1; cvt.u32.u64 %0, t; }" : "=r"(a) : "l"(p));
    return a;
}
#define LDSM_X4(r0, r1, r2, r3, addr) \
    asm volatile("ldmatrix.sync.aligned.m8n8.x4.shared.b16 {%0,%1,%2,%3}, [%4];" \
                 : "=r"(r0), "=r"(r1), "=r"(r2), "=r"(r3) : "r"(addr))
#define MMA_BF16(c, a, b) \
    asm volatile("mma.sync.aligned.m16n8k16.row.col.f32.bf16.bf16.f32 " \
                 "{%0,%1,%2,%3}, {%4,%5,%6,%7}, {%8,%9}, {%0,%1,%2,%3};" \
                 : "+f"((c)[0]), "+f"((c)[1]), "+f"((c)[2]), "+f"((c)[3]) \
                 : "r"((a)[0]), "r"((a)[1]), "r"((a)[2]), "r"((a)[3]), "r"((b)[0]), "r"((b)[1]))
#define CP_ASYNC16(dst, src) \
    asm volatile("cp.async.cg.shared.global [%0], [%1], 16;" :: "r"(dst), "l"(src))
#define CP_COMMIT() asm volatile("cp.async.commit_group;" ::: "memory")
#define CP_WAIT2()  asm volatile("cp.async.wait_group 2;" ::: "memory")

// packed top-k key: ordered-float (desc) || ~idx — one u64 compare == jax tie rule
__device__ __forceinline__ u64 mkkey(float v, int idx) {
    uint32_t u = __float_as_uint(v);
    u = (u & 0x80000000u) ? ~u : (u | 0x80000000u);
    return ((u64)u << 32) | (u64)(0xFFFFFFFFu - (uint32_t)idx);
}
template <int K>
__device__ __forceinline__ void insKey(u64* lst, u64 k) {
    if (k <= lst[K - 1]) return;
    bool b[K];
#pragma unroll
    for (int r = 0; r < K; r++) b[r] = k > lst[r];
#pragma unroll
    for (int r = K - 1; r > 0; r--) lst[r] = b[r - 1] ? lst[r - 1] : (b[r] ? k : lst[r]);
    if (b[0]) lst[0] = k;
}
__device__ __forceinline__ bool better(float x, int xi, float v, int vi) {
    return (x > v) || (x == v && xi < vi);
}
template <int K>
__device__ __forceinline__ void insertK(float* v, int* id, float x, int xi) {
    if (!better(x, xi, v[K - 1], id[K - 1])) return;
    bool b[K];
#pragma unroll
    for (int r = 0; r < K; r++) b[r] = better(x, xi, v[r], id[r]);
#pragma unroll
    for (int r = K - 1; r > 0; r--) {
        v[r]  = b[r - 1] ? v[r - 1]  : (b[r] ? x  : v[r]);
        id[r] = b[r - 1] ? id[r - 1] : (b[r] ? xi : id[r]);
    }
    if (b[0]) { v[0] = x; id[0] = xi; }
}

// ============================================================
// 1) row L2-normalize + bf16 copies — warp per row
// ============================================================
__global__ void __launch_bounds__(256) normalize_kernel(const float* __restrict__ qimg,
                                                        const float* __restrict__ simg) {
    const int t = threadIdx.x, lane = t & 31;
    const int row = blockIdx.x * 8 + (t >> 5);
    const float* src; float* dst; __nv_bfloat16* bdst;
    if (row < Q) { src = qimg + (size_t)row * C;       dst = g_qn + (size_t)row * C; bdst = g_qb + (size_t)row * C; }
    else         { src = simg + (size_t)(row - Q) * C; dst = g_sn + (size_t)(row - Q) * C; bdst = g_sb + (size_t)(row - Q) * C; }

    float4 v[8];
    float ss = 0.f;
#pragma unroll
    for (int i = 0; i < 8; i++) {
        v[i] = ((const float4*)src)[i * 32 + lane];
        ss += v[i].x * v[i].x + v[i].y * v[i].y + v[i].z * v[i].z + v[i].w * v[i].w;
    }
#pragma unroll
    for (int o = 16; o > 0; o >>= 1) ss += __shfl_xor_sync(0xffffffffu, ss, o);
    const float dn = fmaxf(sqrtf(ss), 1e-12f);
#pragma unroll
    for (int i = 0; i < 8; i++) {
        float4 o4;
        o4.x = v[i].x / dn; o4.y = v[i].y / dn; o4.z = v[i].z / dn; o4.w = v[i].w / dn;
        ((float4*)dst)[i * 32 + lane] = o4;
        __nv_bfloat162 b0, b1;
        b0.x = __float2bfloat16(o4.x); b0.y = __float2bfloat16(o4.y);
        b1.x = __float2bfloat16(o4.z); b1.y = __float2bfloat16(o4.w);
        ((__nv_bfloat162*)bdst)[(i * 32 + lane) * 2]     = b0;
        ((__nv_bfloat162*)bdst)[(i * 32 + lane) * 2 + 1] = b1;
    }
}

// ============================================================
// 2a) prototype partial sums: grid (64 classes, 8 s-stripes)
// ============================================================
__global__ void __launch_bounds__(256) proto_part_kernel(const int* __restrict__ labels) {
    __shared__ int slab[512];
    const int w = blockIdx.x, p = blockIdx.y, t = threadIdx.x;
    const int s0 = p * 512;
    for (int i = t; i < 512; i += 256) slab[i] = labels[s0 + i];
    __syncthreads();
    float ax = 0.f, ay = 0.f, az = 0.f, aw = 0.f;
    int cnt = 0;
    for (int s = 0; s < 512; s++) {
        if (slab[s] == w) {
            float4 v = ((const float4*)(g_sn + (size_t)(s0 + s) * C))[t];
            ax += v.x; ay += v.y; az += v.z; aw += v.w; cnt++;
        }
    }
    ((float4*)(g_ppart + ((size_t)w * 8 + p) * C))[t] = make_float4(ax, ay, az, aw);
    if (t == 0) g_pcnt[w * 8 + p] = cnt;
}

// ============================================================
// 2b) combine partials (fixed order), mean, l2norm -> fp32 k-major protoT
// ============================================================
__global__ void __launch_bounds__(256) proto_combine_kernel() {
    __shared__ float red[9];
    const int w = blockIdx.x, t = threadIdx.x;
    float ax = 0.f, ay = 0.f, az = 0.f, aw = 0.f;
    int cnt = 0;
#pragma unroll
    for (int p = 0; p < 8; p++) {
        float4 v = ((const float4*)(g_ppart + ((size_t)w * 8 + p) * C))[t];
        ax += v.x; ay += v.y; az += v.z; aw += v.w;
        cnt += g_pcnt[w * 8 + p];
    }
    const float fc = (float)(cnt > 0 ? cnt : 1);
    ax /= fc; ay /= fc; az /= fc; aw /= fc;
    float ss = ax * ax + ay * ay + az * az + aw * aw;
#pragma unroll
    for (int o = 16; o > 0; o >>= 1) ss += __shfl_xor_sync(0xffffffffu, ss, o);
    if ((t & 31) == 0) red[t >> 5] = ss;
    __syncthreads();
    if (t == 0) {
        float s = 0.f;
#pragma unroll
        for (int i = 0; i < 8; i++) s += red[i];
        red[8] = fmaxf(sqrtf(s), 1e-12f);
    }
    __syncthreads();
    const float dn = red[8];
    const int c0 = t * 4;
    g_protoT[(c0 + 0) * WAY + w] = ax / dn;
    g_protoT[(c0 + 1) * WAY + w] = ay / dn;
    g_protoT[(c0 + 2) * WAY + w] = az / dn;
    g_protoT[(c0 + 3) * WAY + w] = aw / dn;
}

// ============================================================
// 3) bf16 HMMA sim GEMM — proven R6 loop; SPLITS=4 -> 256 CTAs = 1 wave
//    grid (64 q-tiles, 4 s-splits), 256 threads (4m x 2n warps), 2 CTA/SM
// ============================================================
constexpr int STAGE = 128 * RS;              // 10240 B per operand stage
constexpr int SM_A  = 0;                     // 4 stages A
constexpr int SM_B  = NST * STAGE;           // 4 stages B
constexpr int SM_DK = 2 * NST * STAGE;       // 128 x TOPC u64
constexpr int SM_TOTAL_SIM = SM_DK + 128 * TOPC * 8;   // 87040

__global__ void __launch_bounds__(256, 2) sim_topk_kernel() {
    extern __shared__ __align__(16) unsigned char smem[];
    const uint32_t sbase = smem_to_u32(smem);
    const int t = threadIdx.x;
    const int lane = t & 31, wid = t >> 5;
    const int warp_m = wid & 3, warp_n = wid >> 2;
    const int qb = blockIdx.x * 128;
    const int split = blockIdx.y;

    // g2s: thread covers rows r0 and r0+64, 16B segment s0 of the 64B chunk row
    const int r0 = t >> 2, s0 = t & 3;
    const char* gqA = (const char*)g_qb + (size_t)(qb + r0) * 2048 + s0 * 16;
    const char* gqB = (const char*)g_qb + (size_t)(qb + r0 + 64) * 2048 + s0 * 16;
    const uint32_t dA0 = sbase + SM_A + r0 * RS + s0 * 16;
    const uint32_t dA1 = sbase + SM_A + (r0 + 64) * RS + s0 * 16;
    const uint32_t dB0 = sbase + SM_B + r0 * RS + s0 * 16;
    const uint32_t dB1 = sbase + SM_B + (r0 + 64) * RS + s0 * 16;

    // ldmatrix offsets
    const uint32_t aoff0 = sbase + SM_A + (warp_m * 32 + (lane & 15)) * RS + (lane >> 4) * 16;
    const uint32_t boffN = sbase + SM_B + (warp_n * 64 + (lane & 7) + ((lane & 16) ? 8 : 0)) * RS +
                           ((lane >> 3) & 1) * 16;

    u64 key[4][TOPC];
#pragma unroll
    for (int s = 0; s < 4; s++)
#pragma unroll
        for (int r = 0; r < TOPC; r++) key[s][r] = 0;

    for (int st = 0; st < NSUB; st++) {
        const int sr = split * (NSUB * 128) + st * 128;
        const char* gsA = (const char*)g_sb + (size_t)(sr + r0) * 2048 + s0 * 16;
        const char* gsB = (const char*)g_sb + (size_t)(sr + r0 + 64) * 2048 + s0 * 16;
        float c[2][8][4];
#pragma unroll
        for (int mf = 0; mf < 2; mf++)
#pragma unroll
            for (int nf = 0; nf < 8; nf++)
#pragma unroll
                for (int k = 0; k < 4; k++) c[mf][nf][k] = 0.f;

        // prologue: stages 0..2
#pragma unroll
        for (int p = 0; p < NST - 1; p++) {
            const uint32_t so = p * STAGE;
            CP_ASYNC16(dA0 + so, gqA + p * 64);
            CP_ASYNC16(dA1 + so, gqB + p * 64);
            CP_ASYNC16(dB0 + so, gsA + p * 64);
            CP_ASYNC16(dB1 + so, gsB + p * 64);
            CP_COMMIT();
        }

        for (int cc = 0; cc < 32; cc++) {
            CP_WAIT2();
            __syncthreads();
            if (cc < 29) {
                const uint32_t so = ((cc + 3) & 3) * STAGE;
                CP_ASYNC16(dA0 + so, gqA + (cc + 3) * 64);
                CP_ASYNC16(dA1 + so, gqB + (cc + 3) * 64);
                CP_ASYNC16(dB0 + so, gsA + (cc + 3) * 64);
                CP_ASYNC16(dB1 + so, gsB + (cc + 3) * 64);
            }
            CP_COMMIT();
            const uint32_t so = (cc & 3) * STAGE;
#pragma unroll
            for (int ks = 0; ks < 2; ks++) {
                uint32_t af[2][4], bf[8][2];
#pragma unroll
                for (int mf = 0; mf < 2; mf++)
                    LDSM_X4(af[mf][0], af[mf][1], af[mf][2], af[mf][3],
                            aoff0 + so + mf * 16 * RS + ks * 32);
#pragma unroll
                for (int np = 0; np < 4; np++)
                    LDSM_X4(bf[np * 2][0], bf[np * 2][1], bf[np * 2 + 1][0], bf[np * 2 + 1][1],
                            boffN + so + np * 16 * RS + ks * 32);
#pragma unroll
                for (int mf = 0; mf < 2; mf++)
#pragma unroll
                    for (int nf = 0; nf < 8; nf++)
                        MMA_BF16(c[mf][nf], af[mf], bf[nf]);
            }
        }

        // fold subtile into packed top-5 lists
#pragma unroll
        for (int mf = 0; mf < 2; mf++)
#pragma unroll
            for (int nf = 0; nf < 8; nf++) {
                const int col = sr + warp_n * 64 + nf * 8 + (lane & 3) * 2;
                insKey<TOPC>(key[mf * 2],     mkkey(c[mf][nf][0], col));
                insKey<TOPC>(key[mf * 2],     mkkey(c[mf][nf][1], col + 1));
                insKey<TOPC>(key[mf * 2 + 1], mkkey(c[mf][nf][2], col));
                insKey<TOPC>(key[mf * 2 + 1], mkkey(c[mf][nf][3], col + 1));
            }
        __syncthreads();  // protect next subtile's prologue overwrites
    }

    // quad merge (lanes sharing rows differ only in lane&3)
#pragma unroll
    for (int off = 1; off < 4; off <<= 1) {
#pragma unroll
        for (int s = 0; s < 4; s++) {
            u64 ok[TOPC];
#pragma unroll
            for (int r = 0; r < TOPC; r++) ok[r] = __shfl_xor_sync(0xffffffffu, key[s][r], off);
#pragma unroll
            for (int r = 0; r < TOPC; r++) insKey<TOPC>(key[s], ok[r]);
        }
    }

    // cross-warp_n merge via smem, then write per-(query, split) key partials
    u64* dkey = (u64*)(smem + SM_DK);
    const int g = lane >> 2;
    if (warp_n == 1 && (lane & 3) == 0) {
#pragma unroll
        for (int s = 0; s < 4; s++) {
            const int row = warp_m * 32 + (s >> 1) * 16 + (s & 1) * 8 + g;
#pragma unroll
            for (int r = 0; r < TOPC; r++) dkey[row * TOPC + r] = key[s][r];
        }
    }
    __syncthreads();
    if (warp_n == 0 && (lane & 3) == 0) {
#pragma unroll
        for (int s = 0; s < 4; s++) {
            const int row = warp_m * 32 + (s >> 1) * 16 + (s & 1) * 8 + g;
#pragma unroll
            for (int r = 0; r < TOPC; r++) insKey<TOPC>(key[s], dkey[row * TOPC + r]);
            const size_t base = ((size_t)(qb + row) * SPLITS + split) * TOPC;
#pragma unroll
            for (int r = 0; r < TOPC; r++) g_pkey[base + r] = key[s][r];
        }
    }
}

// ============================================================
// 4) warp-parallel merge (20 keys -> top-10), exact fp32 rescore, emit
// ============================================================
__global__ void __launch_bounds__(256) merge_rescore_kernel(const int* __restrict__ labels,
                                                            float* __restrict__ out) {
    __shared__ int   ssel[8][RESC];
    __shared__ float sres[8][RESC];
    const int t = threadIdx.x, wid = t >> 5, lid = t & 31;
    const int q = blockIdx.x * 8 + wid;

    u64 k0 = (lid < NCAND) ? g_pkey[(size_t)q * NCAND + lid] : 0;

#pragma unroll
    for (int i = 0; i < RESC; i++) {
        u64 m = k0;
#pragma unroll
        for (int off = 16; off > 0; off >>= 1) {
            u64 o = __shfl_xor_sync(0xffffffffu, m, off);
            if (o > m) m = o;
        }
        if (lid == 0) ssel[wid][i] = (int)(0xFFFFFFFFu - (uint32_t)m);
        if (k0 == m) k0 = 0;
    }
    __syncwarp();

    float4 qv[8];
#pragma unroll
    for (int k = 0; k < 8; k++)
        qv[k] = *(const float4*)(g_qn + (size_t)q * C + k * 128 + lid * 4);

#pragma unroll 1
    for (int c = 0; c < RESC; c++) {
        const int si = ssel[wid][c];
        const float* srow = g_sn + (size_t)si * C;
        float acc = 0.f;
#pragma unroll
        for (int k = 0; k < 8; k++) {
            float4 sv = *(const float4*)(srow + k * 128 + lid * 4);
            acc = fmaf(qv[k].x, sv.x, acc);
            acc = fmaf(qv[k].y, sv.y, acc);
            acc = fmaf(qv[k].z, sv.z, acc);
            acc = fmaf(qv[k].w, sv.w, acc);
        }
#pragma unroll
        for (int o = 16; o > 0; o >>= 1) acc += __shfl_xor_sync(0xffffffffu, acc, o);
        if (lid == 0) sres[wid][c] = acc;
    }
    __syncwarp();

    if (lid == 0) {
        float v5[5]; int i5[5];
#pragma unroll
        for (int r = 0; r < 5; r++) { v5[r] = -FLT_MAX; i5[r] = 0x7fffffff; }
#pragma unroll
        for (int c = 0; c < RESC; c++) insertK<5>(v5, i5, sres[wid][c], ssel[wid][c]);
#pragma unroll
        for (int r = 0; r < 5; r++) {
            out[OFF_IDX + q * 5 + r] = (float)i5[r];
            out[OFF_DIST + q * 5 + r] = 1.0f - v5[r];
        }
        int lab[5];
#pragma unroll
        for (int r = 0; r < 5; r++) lab[r] = labels[i5[r]];
        int bestc = 0, bestl = 1 << 30;
#pragma unroll
        for (int r = 0; r < 5; r++) {
            int cn = 0;
#pragma unroll
            for (int j = 0; j < 5; j++) cn += (lab[j] == lab[r]);
            if (cn > bestc || (cn == bestc && lab[r] < bestl)) { bestc = cn; bestl = lab[r]; }
        }
        out[OFF_PRED + q] = (float)bestl;
    }
}

// ============================================================
// 5) fp32 scores = q_norm @ protoT -> classification_scores (10x) + scores
// ============================================================
__global__ void __launch_bounds__(256) scores_kernel(float* __restrict__ out) {
    __shared__ __align__(16) float Aq[16][64];
    __shared__ __align__(16) float Bp[16][64];
    const int t = threadIdx.x;
    const int tx = t & 15, ty = t >> 4;
    const int qb = blockIdx.x * 64;
    float acc[4][4];
#pragma unroll
    for (int i = 0; i < 4; i++)
#pragma unroll
        for (int j = 0; j < 4; j++) acc[i][j] = 0.f;

    const int arow = t >> 2, akq = (t & 3) << 2;
    const int bkr = t >> 4, bwq = (t & 15) << 2;
    for (int kc = 0; kc < C; kc += 16) {
        float4 a = *(const float4*)(g_qn + (size_t)(qb + arow) * C + kc + akq);
        Aq[akq + 0][arow] = a.x; Aq[akq + 1][arow] = a.y;
        Aq[akq + 2][arow] = a.z; Aq[akq + 3][arow] = a.w;
        *(float4*)(&Bp[bkr][bwq]) = *(const float4*)(g_protoT + (size_t)(kc + bkr) * WAY + bwq);
        __syncthreads();
#pragma unroll
        for (int k = 0; k < 16; k++) {
            float4 av = *(const float4*)(&Aq[k][ty * 4]);
            float4 bv = *(const float4*)(&Bp[k][tx * 4]);
            float aa[4] = {av.x, av.y, av.z, av.w};
            float bb[4] = {bv.x, bv.y, bv.z, bv.w};
#pragma unroll
            for (int i = 0; i < 4; i++)
#pragma unroll
                for (int j = 0; j < 4; j++) acc[i][j] = fmaf(aa[i], bb[j], acc[i][j]);
        }
        __syncthreads();
    }
#pragma unroll
    for (int i = 0; i < 4; i++) {
        int q = qb + ty * 4 + i;
#pragma unroll
        for (int j = 0; j < 4; j++) {
            int w = tx * 4 + j;
            float s = acc[i][j];
            out[OFF_SC + (size_t)q * WAY + w] = s;
            out[OFF_CLS + (size_t)q * WAY + w] = 10.0f * s;
        }
    }
}

extern "C" void kernel_launch(void* const* d_in, const int* in_sizes, int n_in,
                              void* d_out, int out_size) {
    const float* simg   = (const float*)d_in[0];
    const int*   labels = (const int*)d_in[1];
    const float* qimg   = (const float*)d_in[2];
    float* out = (float*)d_out;

    cudaFuncSetAttribute(sim_topk_kernel, cudaFuncAttributeMaxDynamicSharedMemorySize, SM_TOTAL_SIM);

    // fork: proto chain + scores run on side stream, overlapped with sim
    cudaStream_t s2;
    cudaStreamCreateWithFlags(&s2, cudaStreamNonBlocking);
    cudaEvent_t evA, evB;
    cudaEventCreateWithFlags(&evA, cudaEventDisableTiming);
    cudaEventCreateWithFlags(&evB, cudaEventDisableTiming);

    normalize_kernel<<<(Q + S) / 8, 256>>>(qimg, simg);
    cudaEventRecord(evA, 0);

    cudaStreamWaitEvent(s2, evA, 0);
    proto_part_kernel<<<dim3(WAY, 8), 256, 0, s2>>>(labels);
    proto_combine_kernel<<<WAY, 256, 0, s2>>>();
    scores_kernel<<<Q / 64, 256, 0, s2>>>(out);
    cudaEventRecord(evB, s2);

    sim_topk_kernel<<<dim3(Q / 128, SPLITS), 256, SM_TOTAL_SIM>>>();
    merge_rescore_kernel<<<Q / 8, 256>>>(labels, out);
    cudaStreamWaitEvent(0, evB, 0);
}

// round 17
// speedup vs baseline: 1.0765x; 1.0084x over previous
#include <cuda_runtime.h>
#include <cuda_bf16.h>
#include <cstdint>
#include <cfloat>
#include <math.h>

#define Q 8192
#define S 4096
#define C 1024
#define WAY 64
#define KNN 5

// output layout: tuple flattened in return order (float32)
constexpr int OFF_CLS  = 0;                  // [Q,64]
constexpr int OFF_IDX  = Q * WAY;            // [Q,5]
constexpr int OFF_DIST = OFF_IDX + Q * KNN;  // [Q,5]
constexpr int OFF_PRED = OFF_DIST + Q * KNN; // [Q]
constexpr int OFF_SC   = OFF_PRED + Q;       // [Q,64]

#define SPLITS 4               // s-splits of 1024 supports -> 256 CTAs = 1 full wave
#define NSUB 8                 // 128-support subtiles per split
#define TOPC 5
#define RESC 10
#define NCAND (SPLITS * TOPC)  // 20
#define RS 80                  // smem row stride (64B data + 16B pad)
#define NST 4                  // cp.async pipeline stages

typedef unsigned long long u64;

// scratch (device globals: allocation-free)
__device__ float          g_qn[Q * C];
__device__ float          g_sn[S * C];
__device__ __nv_bfloat16  g_qb[Q * C];
__device__ __nv_bfloat16  g_sb[S * C];
__device__ float          g_protoT[C * WAY];   // fp32 prototypes, k-major
__device__ float          g_ppart[WAY * 8 * C];
__device__ int            g_pcnt[WAY * 8];
__device__ u64            g_pkey[Q * NCAND];

__device__ __forceinline__ uint32_t smem_to_u32(const void* p) {
    uint32_t a;
    asm("{ .reg .u64 t; cvta.to.shared.u64 t, %1; cvt.u32.u64 %0, t; }" : "=r"(a) : "l"(p));
    return a;
}
#define LDSM_X4(r0, r1, r2, r3, addr) \
    asm volatile("ldmatrix.sync.aligned.m8n8.x4.shared.b16 {%0,%1,%2,%3}, [%4];" \
                 : "=r"(r0), "=r"(r1), "=r"(r2), "=r"(r3) : "r"(addr))
#define MMA_BF16(c, a, b) \
    asm volatile("mma.sync.aligned.m16n8k16.row.col.f32.bf16.bf16.f32 " \
                 "{%0,%1,%2,%3}, {%4,%5,%6,%7}, {%8,%9}, {%0,%1,%2,%3};" \
                 : "+f"((c)[0]), "+f"((c)[1]), "+f"((c)[2]), "+f"((c)[3]) \
                 : "r"((a)[0]), "r"((a)[1]), "r"((a)[2]), "r"((a)[3]), "r"((b)[0]), "r"((b)[1]))
#define CP_ASYNC16(dst, src) \
    asm volatile("cp.async.cg.shared.global [%0], [%1], 16;" :: "r"(dst), "l"(src))
#define CP_COMMIT() asm volatile("cp.async.commit_group;" ::: "memory")
#define CP_WAIT2()  asm volatile("cp.async.wait_group 2;" ::: "memory")

// packed top-k key: ordered-float (desc) || ~idx — one u64 compare == jax tie rule
__device__ __forceinline__ u64 mkkey(float v, int idx) {
    uint32_t u = __float_as_uint(v);
    u = (u & 0x80000000u) ? ~u : (u | 0x80000000u);
    return ((u64)u << 32) | (u64)(0xFFFFFFFFu - (uint32_t)idx);
}
template <int K>
__device__ __forceinline__ void insKey(u64* lst, u64 k) {
    if (k <= lst[K - 1]) return;
    bool b[K];
#pragma unroll
    for (int r = 0; r < K; r++) b[r] = k > lst[r];
#pragma unroll
    for (int r = K - 1; r > 0; r--) lst[r] = b[r - 1] ? lst[r - 1] : (b[r] ? k : lst[r]);
    if (b[0]) lst[0] = k;
}
__device__ __forceinline__ bool better(float x, int xi, float v, int vi) {
    return (x > v) || (x == v && xi < vi);
}
template <int K>
__device__ __forceinline__ void insertK(float* v, int* id, float x, int xi) {
    if (!better(x, xi, v[K - 1], id[K - 1])) return;
    bool b[K];
#pragma unroll
    for (int r = 0; r < K; r++) b[r] = better(x, xi, v[r], id[r]);
#pragma unroll
    for (int r = K - 1; r > 0; r--) {
        v[r]  = b[r - 1] ? v[r - 1]  : (b[r] ? x  : v[r]);
        id[r] = b[r - 1] ? id[r - 1] : (b[r] ? xi : id[r]);
    }
    if (b[0]) { v[0] = x; id[0] = xi; }
}

// ============================================================
// 1) row L2-normalize + bf16 copies — warp per row
// ============================================================
__global__ void __launch_bounds__(256) normalize_kernel(const float* __restrict__ qimg,
                                                        const float* __restrict__ simg) {
    const int t = threadIdx.x, lane = t & 31;
    const int row = blockIdx.x * 8 + (t >> 5);
    const float* src; float* dst; __nv_bfloat16* bdst;
    if (row < Q) { src = qimg + (size_t)row * C;       dst = g_qn + (size_t)row * C; bdst = g_qb + (size_t)row * C; }
    else         { src = simg + (size_t)(row - Q) * C; dst = g_sn + (size_t)(row - Q) * C; bdst = g_sb + (size_t)(row - Q) * C; }

    float4 v[8];
    float ss = 0.f;
#pragma unroll
    for (int i = 0; i < 8; i++) {
        v[i] = ((const float4*)src)[i * 32 + lane];
        ss += v[i].x * v[i].x + v[i].y * v[i].y + v[i].z * v[i].z + v[i].w * v[i].w;
    }
#pragma unroll
    for (int o = 16; o > 0; o >>= 1) ss += __shfl_xor_sync(0xffffffffu, ss, o);
    const float dn = fmaxf(sqrtf(ss), 1e-12f);
#pragma unroll
    for (int i = 0; i < 8; i++) {
        float4 o4;
        o4.x = v[i].x / dn; o4.y = v[i].y / dn; o4.z = v[i].z / dn; o4.w = v[i].w / dn;
        ((float4*)dst)[i * 32 + lane] = o4;
        __nv_bfloat162 b0, b1;
        b0.x = __float2bfloat16(o4.x); b0.y = __float2bfloat16(o4.y);
        b1.x = __float2bfloat16(o4.z); b1.y = __float2bfloat16(o4.w);
        ((__nv_bfloat162*)bdst)[(i * 32 + lane) * 2]     = b0;
        ((__nv_bfloat162*)bdst)[(i * 32 + lane) * 2 + 1] = b1;
    }
}

// ============================================================
// 2a) prototype partial sums: grid (64 classes, 8 s-stripes)
// ============================================================
__global__ void __launch_bounds__(256) proto_part_kernel(const int* __restrict__ labels) {
    __shared__ int slab[512];
    const int w = blockIdx.x, p = blockIdx.y, t = threadIdx.x;
    const int s0 = p * 512;
    for (int i = t; i < 512; i += 256) slab[i] = labels[s0 + i];
    __syncthreads();
    float ax = 0.f, ay = 0.f, az = 0.f, aw = 0.f;
    int cnt = 0;
    for (int s = 0; s < 512; s++) {
        if (slab[s] == w) {
            float4 v = ((const float4*)(g_sn + (size_t)(s0 + s) * C))[t];
            ax += v.x; ay += v.y; az += v.z; aw += v.w; cnt++;
        }
    }
    ((float4*)(g_ppart + ((size_t)w * 8 + p) * C))[t] = make_float4(ax, ay, az, aw);
    if (t == 0) g_pcnt[w * 8 + p] = cnt;
}

// ============================================================
// 2b) combine partials (fixed order), mean, l2norm -> fp32 k-major protoT
// ============================================================
__global__ void __launch_bounds__(256) proto_combine_kernel() {
    __shared__ float red[9];
    const int w = blockIdx.x, t = threadIdx.x;
    float ax = 0.f, ay = 0.f, az = 0.f, aw = 0.f;
    int cnt = 0;
#pragma unroll
    for (int p = 0; p < 8; p++) {
        float4 v = ((const float4*)(g_ppart + ((size_t)w * 8 + p) * C))[t];
        ax += v.x; ay += v.y; az += v.z; aw += v.w;
        cnt += g_pcnt[w * 8 + p];
    }
    const float fc = (float)(cnt > 0 ? cnt : 1);
    ax /= fc; ay /= fc; az /= fc; aw /= fc;
    float ss = ax * ax + ay * ay + az * az + aw * aw;
#pragma unroll
    for (int o = 16; o > 0; o >>= 1) ss += __shfl_xor_sync(0xffffffffu, ss, o);
    if ((t & 31) == 0) red[t >> 5] = ss;
    __syncthreads();
    if (t == 0) {
        float s = 0.f;
#pragma unroll
        for (int i = 0; i < 8; i++) s += red[i];
        red[8] = fmaxf(sqrtf(s), 1e-12f);
    }
    __syncthreads();
    const float dn = red[8];
    const int c0 = t * 4;
    g_protoT[(c0 + 0) * WAY + w] = ax / dn;
    g_protoT[(c0 + 1) * WAY + w] = ay / dn;
    g_protoT[(c0 + 2) * WAY + w] = az / dn;
    g_protoT[(c0 + 3) * WAY + w] = aw / dn;
}

// ============================================================
// 3) bf16 HMMA sim GEMM — proven R6 loop; SPLITS=4 -> 256 CTAs = 1 wave
//    grid (64 q-tiles, 4 s-splits), 256 threads (4m x 2n warps), 2 CTA/SM
// ============================================================
constexpr int STAGE = 128 * RS;              // 10240 B per operand stage
constexpr int SM_A  = 0;                     // 4 stages A
constexpr int SM_B  = NST * STAGE;           // 4 stages B
constexpr int SM_DK = 2 * NST * STAGE;       // 128 x TOPC u64
constexpr int SM_TOTAL_SIM = SM_DK + 128 * TOPC * 8;   // 87040

__global__ void __launch_bounds__(256, 2) sim_topk_kernel() {
    extern __shared__ __align__(16) unsigned char smem[];
    const uint32_t sbase = smem_to_u32(smem);
    const int t = threadIdx.x;
    const int lane = t & 31, wid = t >> 5;
    const int warp_m = wid & 3, warp_n = wid >> 2;
    const int qb = blockIdx.x * 128;
    const int split = blockIdx.y;

    // g2s: thread covers rows r0 and r0+64, 16B segment s0 of the 64B chunk row
    const int r0 = t >> 2, s0 = t & 3;
    const char* gqA = (const char*)g_qb + (size_t)(qb + r0) * 2048 + s0 * 16;
    const char* gqB = (const char*)g_qb + (size_t)(qb + r0 + 64) * 2048 + s0 * 16;
    const uint32_t dA0 = sbase + SM_A + r0 * RS + s0 * 16;
    const uint32_t dA1 = sbase + SM_A + (r0 + 64) * RS + s0 * 16;
    const uint32_t dB0 = sbase + SM_B + r0 * RS + s0 * 16;
    const uint32_t dB1 = sbase + SM_B + (r0 + 64) * RS + s0 * 16;

    // ldmatrix offsets
    const uint32_t aoff0 = sbase + SM_A + (warp_m * 32 + (lane & 15)) * RS + (lane >> 4) * 16;
    const uint32_t boffN = sbase + SM_B + (warp_n * 64 + (lane & 7) + ((lane & 16) ? 8 : 0)) * RS +
                           ((lane >> 3) & 1) * 16;

    u64 key[4][TOPC];
#pragma unroll
    for (int s = 0; s < 4; s++)
#pragma unroll
        for (int r = 0; r < TOPC; r++) key[s][r] = 0;

    for (int st = 0; st < NSUB; st++) {
        const int sr = split * (NSUB * 128) + st * 128;
        const char* gsA = (const char*)g_sb + (size_t)(sr + r0) * 2048 + s0 * 16;
        const char* gsB = (const char*)g_sb + (size_t)(sr + r0 + 64) * 2048 + s0 * 16;
        float c[2][8][4];
#pragma unroll
        for (int mf = 0; mf < 2; mf++)
#pragma unroll
            for (int nf = 0; nf < 8; nf++)
#pragma unroll
                for (int k = 0; k < 4; k++) c[mf][nf][k] = 0.f;

        // prologue: stages 0..2
#pragma unroll
        for (int p = 0; p < NST - 1; p++) {
            const uint32_t so = p * STAGE;
            CP_ASYNC16(dA0 + so, gqA + p * 64);
            CP_ASYNC16(dA1 + so, gqB + p * 64);
            CP_ASYNC16(dB0 + so, gsA + p * 64);
            CP_ASYNC16(dB1 + so, gsB + p * 64);
            CP_COMMIT();
        }

        for (int cc = 0; cc < 32; cc++) {
            CP_WAIT2();
            __syncthreads();
            if (cc < 29) {
                const uint32_t so = ((cc + 3) & 3) * STAGE;
                CP_ASYNC16(dA0 + so, gqA + (cc + 3) * 64);
                CP_ASYNC16(dA1 + so, gqB + (cc + 3) * 64);
                CP_ASYNC16(dB0 + so, gsA + (cc + 3) * 64);
                CP_ASYNC16(dB1 + so, gsB + (cc + 3) * 64);
            }
            CP_COMMIT();
            const uint32_t so = (cc & 3) * STAGE;
#pragma unroll
            for (int ks = 0; ks < 2; ks++) {
                uint32_t af[2][4], bf[8][2];
#pragma unroll
                for (int mf = 0; mf < 2; mf++)
                    LDSM_X4(af[mf][0], af[mf][1], af[mf][2], af[mf][3],
                            aoff0 + so + mf * 16 * RS + ks * 32);
#pragma unroll
                for (int np = 0; np < 4; np++)
                    LDSM_X4(bf[np * 2][0], bf[np * 2][1], bf[np * 2 + 1][0], bf[np * 2 + 1][1],
                            boffN + so + np * 16 * RS + ks * 32);
#pragma unroll
                for (int mf = 0; mf < 2; mf++)
#pragma unroll
                    for (int nf = 0; nf < 8; nf++)
                        MMA_BF16(c[mf][nf], af[mf], bf[nf]);
            }
        }

        // fold subtile into packed top-5 lists
#pragma unroll
        for (int mf = 0; mf < 2; mf++)
#pragma unroll
            for (int nf = 0; nf < 8; nf++) {
                const int col = sr + warp_n * 64 + nf * 8 + (lane & 3) * 2;
                insKey<TOPC>(key[mf * 2],     mkkey(c[mf][nf][0], col));
                insKey<TOPC>(key[mf * 2],     mkkey(c[mf][nf][1], col + 1));
                insKey<TOPC>(key[mf * 2 + 1], mkkey(c[mf][nf][2], col));
                insKey<TOPC>(key[mf * 2 + 1], mkkey(c[mf][nf][3], col + 1));
            }
        __syncthreads();  // protect next subtile's prologue overwrites
    }

    // quad merge (lanes sharing rows differ only in lane&3)
#pragma unroll
    for (int off = 1; off < 4; off <<= 1) {
#pragma unroll
        for (int s = 0; s < 4; s++) {
            u64 ok[TOPC];
#pragma unroll
            for (int r = 0; r < TOPC; r++) ok[r] = __shfl_xor_sync(0xffffffffu, key[s][r], off);
#pragma unroll
            for (int r = 0; r < TOPC; r++) insKey<TOPC>(key[s], ok[r]);
        }
    }

    // cross-warp_n merge via smem, then write per-(query, split) key partials
    u64* dkey = (u64*)(smem + SM_DK);
    const int g = lane >> 2;
    if (warp_n == 1 && (lane & 3) == 0) {
#pragma unroll
        for (int s = 0; s < 4; s++) {
            const int row = warp_m * 32 + (s >> 1) * 16 + (s & 1) * 8 + g;
#pragma unroll
            for (int r = 0; r < TOPC; r++) dkey[row * TOPC + r] = key[s][r];
        }
    }
    __syncthreads();
    if (warp_n == 0 && (lane & 3) == 0) {
#pragma unroll
        for (int s = 0; s < 4; s++) {
            const int row = warp_m * 32 + (s >> 1) * 16 + (s & 1) * 8 + g;
#pragma unroll
            for (int r = 0; r < TOPC; r++) insKey<TOPC>(key[s], dkey[row * TOPC + r]);
            const size_t base = ((size_t)(qb + row) * SPLITS + split) * TOPC;
#pragma unroll
            for (int r = 0; r < TOPC; r++) g_pkey[base + r] = key[s][r];
        }
    }
}

// ============================================================
// 4) warp-parallel merge (20 keys -> top-10), exact fp32 rescore (2-way ILP)
// ============================================================
__global__ void __launch_bounds__(256) merge_rescore_kernel(const int* __restrict__ labels,
                                                            float* __restrict__ out) {
    __shared__ int   ssel[8][RESC];
    __shared__ float sres[8][RESC];
    const int t = threadIdx.x, wid = t >> 5, lid = t & 31;
    const int q = blockIdx.x * 8 + wid;

    u64 k0 = (lid < NCAND) ? g_pkey[(size_t)q * NCAND + lid] : 0;

#pragma unroll
    for (int i = 0; i < RESC; i++) {
        u64 m = k0;
#pragma unroll
        for (int off = 16; off > 0; off >>= 1) {
            u64 o = __shfl_xor_sync(0xffffffffu, m, off);
            if (o > m) m = o;
        }
        if (lid == 0) ssel[wid][i] = (int)(0xFFFFFFFFu - (uint32_t)m);
        if (k0 == m) k0 = 0;
    }
    __syncwarp();

    float4 qv[8];
#pragma unroll
    for (int k = 0; k < 8; k++)
        qv[k] = *(const float4*)(g_qn + (size_t)q * C + k * 128 + lid * 4);

    // rescore 2 candidates at a time: interleaved load streams double MLP
#pragma unroll 1
    for (int c = 0; c < RESC; c += 2) {
        const int si0 = ssel[wid][c];
        const int si1 = ssel[wid][c + 1];
        const float* srow0 = g_sn + (size_t)si0 * C;
        const float* srow1 = g_sn + (size_t)si1 * C;
        float acc0 = 0.f, acc1 = 0.f;
#pragma unroll
        for (int k = 0; k < 8; k++) {
            float4 sv0 = *(const float4*)(srow0 + k * 128 + lid * 4);
            float4 sv1 = *(const float4*)(srow1 + k * 128 + lid * 4);
            acc0 = fmaf(qv[k].x, sv0.x, acc0);
            acc0 = fmaf(qv[k].y, sv0.y, acc0);
            acc0 = fmaf(qv[k].z, sv0.z, acc0);
            acc0 = fmaf(qv[k].w, sv0.w, acc0);
            acc1 = fmaf(qv[k].x, sv1.x, acc1);
            acc1 = fmaf(qv[k].y, sv1.y, acc1);
            acc1 = fmaf(qv[k].z, sv1.z, acc1);
            acc1 = fmaf(qv[k].w, sv1.w, acc1);
        }
#pragma unroll
        for (int o = 16; o > 0; o >>= 1) {
            acc0 += __shfl_xor_sync(0xffffffffu, acc0, o);
            acc1 += __shfl_xor_sync(0xffffffffu, acc1, o);
        }
        if (lid == 0) { sres[wid][c] = acc0; sres[wid][c + 1] = acc1; }
    }
    __syncwarp();

    if (lid == 0) {
        float v5[5]; int i5[5];
#pragma unroll
        for (int r = 0; r < 5; r++) { v5[r] = -FLT_MAX; i5[r] = 0x7fffffff; }
#pragma unroll
        for (int c = 0; c < RESC; c++) insertK<5>(v5, i5, sres[wid][c], ssel[wid][c]);
#pragma unroll
        for (int r = 0; r < 5; r++) {
            out[OFF_IDX + q * 5 + r] = (float)i5[r];
            out[OFF_DIST + q * 5 + r] = 1.0f - v5[r];
        }
        int lab[5];
#pragma unroll
        for (int r = 0; r < 5; r++) lab[r] = labels[i5[r]];
        int bestc = 0, bestl = 1 << 30;
#pragma unroll
        for (int r = 0; r < 5; r++) {
            int cn = 0;
#pragma unroll
            for (int j = 0; j < 5; j++) cn += (lab[j] == lab[r]);
            if (cn > bestc || (cn == bestc && lab[r] < bestl)) { bestc = cn; bestl = lab[r]; }
        }
        out[OFF_PRED + q] = (float)bestl;
    }
}

// ============================================================
// 5) fp32 scores = q_norm @ protoT -> classification_scores (10x) + scores
// ============================================================
__global__ void __launch_bounds__(256) scores_kernel(float* __restrict__ out) {
    __shared__ __align__(16) float Aq[16][64];
    __shared__ __align__(16) float Bp[16][64];
    const int t = threadIdx.x;
    const int tx = t & 15, ty = t >> 4;
    const int qb = blockIdx.x * 64;
    float acc[4][4];
#pragma unroll
    for (int i = 0; i < 4; i++)
#pragma unroll
        for (int j = 0; j < 4; j++) acc[i][j] = 0.f;

    const int arow = t >> 2, akq = (t & 3) << 2;
    const int bkr = t >> 4, bwq = (t & 15) << 2;
    for (int kc = 0; kc < C; kc += 16) {
        float4 a = *(const float4*)(g_qn + (size_t)(qb + arow) * C + kc + akq);
        Aq[akq + 0][arow] = a.x; Aq[akq + 1][arow] = a.y;
        Aq[akq + 2][arow] = a.z; Aq[akq + 3][arow] = a.w;
        *(float4*)(&Bp[bkr][bwq]) = *(const float4*)(g_protoT + (size_t)(kc + bkr) * WAY + bwq);
        __syncthreads();
#pragma unroll
        for (int k = 0; k < 16; k++) {
            float4 av = *(const float4*)(&Aq[k][ty * 4]);
            float4 bv = *(const float4*)(&Bp[k][tx * 4]);
            float aa[4] = {av.x, av.y, av.z, av.w};
            float bb[4] = {bv.x, bv.y, bv.z, bv.w};
#pragma unroll
            for (int i = 0; i < 4; i++)
#pragma unroll
                for (int j = 0; j < 4; j++) acc[i][j] = fmaf(aa[i], bb[j], acc[i][j]);
        }
        __syncthreads();
    }
#pragma unroll
    for (int i = 0; i < 4; i++) {
        int q = qb + ty * 4 + i;
#pragma unroll
        for (int j = 0; j < 4; j++) {
            int w = tx * 4 + j;
            float s = acc[i][j];
            out[OFF_SC + (size_t)q * WAY + w] = s;
            out[OFF_CLS + (size_t)q * WAY + w] = 10.0f * s;
        }
    }
}

extern "C" void kernel_launch(void* const* d_in, const int* in_sizes, int n_in,
                              void* d_out, int out_size) {
    const float* simg   = (const float*)d_in[0];
    const int*   labels = (const int*)d_in[1];
    const float* qimg   = (const float*)d_in[2];
    float* out = (float*)d_out;

    cudaFuncSetAttribute(sim_topk_kernel, cudaFuncAttributeMaxDynamicSharedMemorySize, SM_TOTAL_SIM);

    // fork: proto chain + scores run on side stream, overlapped with sim
    cudaStream_t s2;
    cudaStreamCreateWithFlags(&s2, cudaStreamNonBlocking);
    cudaEvent_t evA, evB;
    cudaEventCreateWithFlags(&evA, cudaEventDisableTiming);
    cudaEventCreateWithFlags(&evB, cudaEventDisableTiming);

    normalize_kernel<<<(Q + S) / 8, 256>>>(qimg, simg);
    cudaEventRecord(evA, 0);

    cudaStreamWaitEvent(s2, evA, 0);
    proto_part_kernel<<<dim3(WAY, 8), 256, 0, s2>>>(labels);
    proto_combine_kernel<<<WAY, 256, 0, s2>>>();
    scores_kernel<<<Q / 64, 256, 0, s2>>>(out);
    cudaEventRecord(evB, s2);

    sim_topk_kernel<<<dim3(Q / 128, SPLITS), 256, SM_TOTAL_SIM>>>();
    merge_rescore_kernel<<<Q / 8, 256>>>(labels, out);
    cudaStreamWaitEvent(0, evB, 0);
}